// round 14
// baseline (speedup 1.0000x reference)
#include <cuda_runtime.h>
#include <cuda_fp16.h>
#include <cstdint>
#include <cstddef>

// ===================== problem constants =====================
static constexpr int NP      = 50000;     // particles
static constexpr int NPAD    = 50048;     // padded: 391*128
static constexpr int EDG     = 800000;
static constexpr int CAP     = 64;        // slots per receiver (Poisson(16) tail-safe)
static constexpr int KDIM    = 512;       // folded contraction dim: 8 taps * 64 ch
static constexpr int OUTC    = 64;
static constexpr int PD      = 8;         // phase1 cp.async pipeline depth

// scales (exact powers of 2): A*16, B*1024; epilogue * 2^-14
static constexpr float SA      = 16.0f;
static constexpr float SB      = 1024.0f;
static constexpr float INV_SAB = 1.0f / 16384.0f;

// ===================== device scratch (no allocs allowed) =====================
__device__ int    g_deg[NPAD];
__device__ int    g_slotS[(size_t)NPAD * CAP];        // sender per slot
__device__ float4 g_wp[(size_t)NPAD * CAP * 2];       // folded weights, 2 float4 per slot
__device__ __align__(128) __half g_Ah[(size_t)NPAD * KDIM];   // fp16-hi of A*16, [row][512]
__device__ __align__(128) __half g_Al[(size_t)NPAD * KDIM];   // fp16-lo residual
__device__ __align__(128) __half g_Bh[OUTC * KDIM];           // fp16-hi of Kfold^T*1024, [n][k]
__device__ __align__(128) __half g_Bl[OUTC * KDIM];           // fp16-lo residual

// ===================== helpers =====================
__device__ __forceinline__ uint32_t smem_u32(const void* p) {
    return (uint32_t)__cvta_generic_to_shared(p);
}

__device__ __forceinline__ void mma16(float* c, const uint32_t* a, const uint32_t* b) {
    asm volatile(
        "mma.sync.aligned.m16n8k16.row.col.f32.f16.f16.f32 "
        "{%0,%1,%2,%3}, {%4,%5,%6,%7}, {%8,%9}, {%0,%1,%2,%3};"
        : "+f"(c[0]), "+f"(c[1]), "+f"(c[2]), "+f"(c[3])
        : "r"(a[0]), "r"(a[1]), "r"(a[2]), "r"(a[3]), "r"(b[0]), "r"(b[1]));
}

__device__ __forceinline__ void ldsm4(uint32_t* r, uint32_t addr) {
    asm volatile("ldmatrix.sync.aligned.m8n8.x4.shared.b16 {%0,%1,%2,%3}, [%4];"
                 : "=r"(r[0]), "=r"(r[1]), "=r"(r[2]), "=r"(r[3]) : "r"(addr));
}

// ===================== kernel 1: zero degree counters + build folded B (fp16 hi/lo) =====================
__global__ void k_prep(const float* __restrict__ ker) {
    int i = blockIdx.x * blockDim.x + threadIdx.x;
    if (i < NPAD) g_deg[i] = 0;
    if (i < KDIM * OUTC) {
        int n = i / KDIM;
        int k = i % KDIM;
        int t = k / 64, ic = k % 64;
        int x = t / 4, y = t % 4;
        float v;
        if (y < 2) v = ker[(((x * 2 + y) * 64 + ic) * 64) + n];
        else       v = -ker[((((3 - x) * 2 + (3 - y)) * 64 + ic) * 64) + n];
        float vs = v * SB;
        __half h = __float2half_rn(vs);
        __half l = __float2half_rn(vs - __half2float(h));
        g_Bh[n * KDIM + k] = h;
        g_Bl[n * KDIM + k] = l;
    }
}

// ===================== kernel 2: bucket edges + precompute folded weights =====================
__global__ void k_fill(const int* __restrict__ recv, const int* __restrict__ snd,
                       const float* __restrict__ rp, const float* __restrict__ ws_p) {
    int e = blockIdx.x * blockDim.x + threadIdx.x;
    if (e >= EDG) return;
    int r = recv[e];
    int slot = atomicAdd(&g_deg[r], 1);
    if (slot >= CAP) return;

    float inv_ws = 1.0f / (*ws_p);
    float2 p = ((const float2*)rp)[e];
    float ux = fminf(fmaxf(p.x * inv_ws, -1.f), 1.f);
    float uy = fminf(fmaxf(p.y * inv_ws, -1.f), 1.f);
    float gx = (ux + 1.f) * 1.5f;
    float gy = (uy + 1.f) * 1.5f;
    float x0 = fminf(fmaxf(floorf(gx), 0.f), 2.f);
    float y0 = fminf(fmaxf(floorf(gy), 0.f), 2.f);
    float fx = gx - x0, fy = gy - y0;
    int x0i = (int)x0, y0i = (int)y0;
    float r2 = ux * ux + uy * uy;
    float win = fmaxf(1.f - r2, 0.f);
    win = win * win * win;

    float wx[4], wy[4];
    #pragma unroll
    for (int j = 0; j < 4; j++) {
        wx[j] = (j == x0i) ? (1.f - fx) * win : ((j == x0i + 1) ? fx * win : 0.f);
        wy[j] = (j == y0i) ? (1.f - fy)       : ((j == y0i + 1) ? fy       : 0.f);
    }
    float wf[8];
    #pragma unroll
    for (int f = 0; f < 8; f++) {
        int xf = f >> 2, yf = f & 3;
        wf[f] = wx[xf] * wy[yf] - wx[3 - xf] * wy[3 - yf];
    }
    size_t si = (size_t)r * CAP + slot;
    g_slotS[si] = snd[e];
    g_wp[si * 2 + 0] = make_float4(wf[0], wf[1], wf[2], wf[3]);
    g_wp[si * 2 + 1] = make_float4(wf[4], wf[5], wf[6], wf[7]);
}

// ===================== kernel 3: per-receiver aggregation; emits fp16 hi/lo A*16 =====================
__global__ void __launch_bounds__(64) k_phase1(const float* __restrict__ feat) {
    __shared__ float sFeat[2][PD][64];
    __shared__ float sW[2][PD][8];

    int warp = threadIdx.x >> 5, lane = threadIdx.x & 31;
    int r = blockIdx.x * 2 + warp;          // grid = NPAD/2 exactly
    int nd = min(g_deg[r], CAP);            // uniform across warp
    size_t base = (size_t)r * CAP;

    int sl = (lane < nd)      ? g_slotS[base + lane]      : 0;
    int sh = (32 + lane < nd) ? g_slotS[base + 32 + lane] : 0;

    float acc[16];
    #pragma unroll
    for (int j = 0; j < 16; j++) acc[j] = 0.f;

    #define ISSUE(e) do {                                                        \
        int _e = (e);                                                            \
        if (_e < nd) {                                                           \
            int _j = _e & (PD - 1);                                              \
            int _s = __shfl_sync(0xFFFFFFFFu, (_e < 32) ? sl : sh, _e & 31);     \
            if (lane < 16) {                                                     \
                const float4* _src = (const float4*)(feat + (size_t)_s * 64) + lane; \
                uint32_t _dst = smem_u32(&sFeat[warp][_j][lane * 4]);            \
                asm volatile("cp.async.ca.shared.global [%0], [%1], 16;"         \
                             :: "r"(_dst), "l"(_src) : "memory");                \
            } else if (lane < 18) {                                              \
                const float4* _src = &g_wp[(base + _e) * 2 + (lane - 16)];       \
                uint32_t _dst = smem_u32(&sW[warp][_j][(lane - 16) * 4]);        \
                asm volatile("cp.async.ca.shared.global [%0], [%1], 16;"         \
                             :: "r"(_dst), "l"(_src) : "memory");                \
            }                                                                    \
        }                                                                        \
        asm volatile("cp.async.commit_group;" ::: "memory");                     \
    } while (0)

    #define CONSUME(e) do {                                                      \
        int _jb = (e) & (PD - 1);                                                \
        float2 f  = *(const float2*)&sFeat[warp][_jb][lane * 2];                 \
        float4 w0 = *(const float4*)&sW[warp][_jb][0];                           \
        float4 w1 = *(const float4*)&sW[warp][_jb][4];                           \
        acc[0]  += w0.x * f.x;  acc[1]  += w0.x * f.y;                           \
        acc[2]  += w0.y * f.x;  acc[3]  += w0.y * f.y;                           \
        acc[4]  += w0.z * f.x;  acc[5]  += w0.z * f.y;                           \
        acc[6]  += w0.w * f.x;  acc[7]  += w0.w * f.y;                           \
        acc[8]  += w1.x * f.x;  acc[9]  += w1.x * f.y;                           \
        acc[10] += w1.y * f.x;  acc[11] += w1.y * f.y;                           \
        acc[12] += w1.z * f.x;  acc[13] += w1.z * f.y;                           \
        acc[14] += w1.w * f.x;  acc[15] += w1.w * f.y;                           \
    } while (0)

    #pragma unroll
    for (int j = 0; j < PD; j++) ISSUE(j);

    int e = 0;
    for (; e + 3 < nd; e += 4) {
        asm volatile("cp.async.wait_group %0;" :: "n"(PD - 4) : "memory");
        __syncwarp();
        CONSUME(e);
        CONSUME(e + 1);
        CONSUME(e + 2);
        CONSUME(e + 3);
        __syncwarp();
        ISSUE(e + PD);
        ISSUE(e + PD + 1);
        ISSUE(e + PD + 2);
        ISSUE(e + PD + 3);
    }
    if (e < nd) {
        asm volatile("cp.async.wait_group 0;" ::: "memory");
        __syncwarp();
        for (; e < nd; e++) CONSUME(e);
    }
    #undef ISSUE
    #undef CONSUME

    // tail: scale by SA, split to fp16 hi/lo, store as half2 per lane pair
    __half2* dhi = (__half2*)g_Ah + (((size_t)r * KDIM) >> 1) + lane;
    __half2* dlo = (__half2*)g_Al + (((size_t)r * KDIM) >> 1) + lane;
    #pragma unroll
    for (int t = 0; t < 8; t++) {
        float v0 = acc[2 * t] * SA, v1 = acc[2 * t + 1] * SA;
        __half h0 = __float2half_rn(v0);
        __half h1 = __float2half_rn(v1);
        __half l0 = __float2half_rn(v0 - __half2float(h0));
        __half l1 = __float2half_rn(v1 - __half2float(h1));
        dhi[t * 32] = __halves2half2(h0, h1);
        dlo[t * 32] = __halves2half2(l0, l1);
    }
}

// ===================== kernel 4: fp16 3-pass mma GEMM, M=128 tiles, swizzled, 3 CTAs/SM =====================
// out[NPAD(128/CTA), 64] = (Ah+Al)(Bh+Bl)^T * 2^-14 + bias  (drop Al*Bl)
// 8 warps as 4(M) x 2(N); warp tile 32x32; KC=32 halfs (2 k16-steps), 16 chunks, 3 stages.
// smem rows are 64B (32 halfs) with 16B-granule XOR swizzle: chunk' = chunk ^ ((row>>1)&3).
// Conflict-free for cp.async 16B stores and all ldmatrix phases (8 distinct mod-128 positions).
static constexpr int KC     = 32;              // halfs per chunk
static constexpr int A_HI_B = 0;               // byte offsets within a stage
static constexpr int A_LO_B = 8192;            // 128 rows * 64 B
static constexpr int B_HI_B = 16384;
static constexpr int B_LO_B = 20480;           // + 64 rows * 64 B
static constexpr int STG_B  = 24576;           // stage bytes (24 KB)
static constexpr int NCH    = KDIM / KC;       // 16 chunks
static constexpr int GEMM_SMEM = 3 * STG_B;    // 73728 B -> 3 CTAs/SM, single wave

__device__ __forceinline__ uint32_t swz(int row, int chunk) {
    return (uint32_t)(row * 64 + ((chunk ^ ((row >> 1) & 3)) << 4));
}

__global__ void __launch_bounds__(256, 3) k_gemm(const float* __restrict__ bias,
                                                 float* __restrict__ out) {
    extern __shared__ char smc[];

    int tid = threadIdx.x;
    int warp = tid >> 5, lane = tid & 31;
    int gid = lane >> 2, tig = lane & 3;
    int warpM = warp >> 1, warpN = warp & 1;
    int m_base = warpM * 32;
    int n_base = warpN * 32;
    int m0 = blockIdx.x * 128;

    // ldmatrix lane->tile mapping
    int t3  = lane >> 3, rin = lane & 7;
    int a_rl = ((t3 & 1) << 3) + rin;          // row within 16-row group
    int a_ci = t3 >> 1;                        // +chunk for k8-15
    int b_rl = ((t3 >> 1) << 3) + rin;         // n within 16-n group
    int b_ci = t3 & 1;

    // staging granule indices
    int sArow0 = tid >> 2, sAch = tid & 3;     // A: +128 granule rows via i*64... (2 iters of 256)
    // (A has 512 granules: iter i covers granule tid + i*256 -> row (tid>>2)+i*64)

    float acc[2][4][4];
    #pragma unroll
    for (int mt = 0; mt < 2; mt++)
        #pragma unroll
        for (int nt = 0; nt < 4; nt++)
            #pragma unroll
            for (int j = 0; j < 4; j++) acc[mt][nt][j] = 0.f;

    #define STAGE(kc) do {                                                       \
        if ((kc) < NCH) {                                                        \
            char* _st = smc + ((kc) % 3) * STG_B;                                \
            int _gk = (kc) * KC + sAch * 8;                                      \
            _Pragma("unroll")                                                    \
            for (int _i = 0; _i < 2; _i++) {                                     \
                int _row = sArow0 + _i * 64;                                     \
                uint32_t _so = swz(_row, sAch);                                  \
                asm volatile("cp.async.ca.shared.global [%0], [%1], 16;"         \
                    :: "r"(smem_u32(_st + A_HI_B + _so)),                        \
                       "l"(g_Ah + (size_t)(m0 + _row) * KDIM + _gk) : "memory"); \
                asm volatile("cp.async.ca.shared.global [%0], [%1], 16;"         \
                    :: "r"(smem_u32(_st + A_LO_B + _so)),                        \
                       "l"(g_Al + (size_t)(m0 + _row) * KDIM + _gk) : "memory"); \
            }                                                                    \
            {                                                                    \
                int _row = sArow0;        /* 0..63 */                            \
                uint32_t _so = swz(_row, sAch);                                  \
                asm volatile("cp.async.ca.shared.global [%0], [%1], 16;"         \
                    :: "r"(smem_u32(_st + B_HI_B + _so)),                        \
                       "l"(g_Bh + _row * KDIM + _gk) : "memory");                \
                asm volatile("cp.async.ca.shared.global [%0], [%1], 16;"         \
                    :: "r"(smem_u32(_st + B_LO_B + _so)),                        \
                       "l"(g_Bl + _row * KDIM + _gk) : "memory");                \
            }                                                                    \
        }                                                                        \
        asm volatile("cp.async.commit_group;" ::: "memory");                     \
    } while (0)

    // ---- prologue: stage chunks 0,1 ----
    STAGE(0);
    STAGE(1);

    #pragma unroll 1
    for (int kc = 0; kc < NCH; kc++) {
        asm volatile("cp.async.wait_group 1;" ::: "memory");   // chunk kc complete
        __syncthreads();
        STAGE(kc + 2);                                         // slot (kc+2)%3, drained

        char* st = smc + (kc % 3) * STG_B;

        #pragma unroll
        for (int ks = 0; ks < 2; ks++) {
            // B fragments for both 16-n groups
            uint32_t bh[2][4], bl[2][4];
            #pragma unroll
            for (int ng = 0; ng < 2; ng++) {
                int rowB = n_base + ng * 16 + b_rl;
                uint32_t so = swz(rowB, 2 * ks + b_ci);
                ldsm4(bh[ng], smem_u32(st + B_HI_B + so));
                ldsm4(bl[ng], smem_u32(st + B_LO_B + so));
            }
            #pragma unroll
            for (int mt = 0; mt < 2; mt++) {
                uint32_t ah[4], al[4];
                int rowA = m_base + mt * 16 + a_rl;
                uint32_t so = swz(rowA, 2 * ks + a_ci);
                ldsm4(ah, smem_u32(st + A_HI_B + so));
                ldsm4(al, smem_u32(st + A_LO_B + so));
                #pragma unroll
                for (int nt = 0; nt < 4; nt++) {
                    int ng = nt >> 1, of = (nt & 1) * 2;
                    mma16(acc[mt][nt], ah, &bh[ng][of]);
                    mma16(acc[mt][nt], al, &bh[ng][of]);
                    mma16(acc[mt][nt], ah, &bl[ng][of]);
                }
            }
        }
    }
    #undef STAGE

    // ---- epilogue: un-scale + bias + store ----
    #pragma unroll
    for (int mt = 0; mt < 2; mt++) {
        int r  = m0 + m_base + mt * 16 + gid;
        int r8 = r + 8;
        #pragma unroll
        for (int nt = 0; nt < 4; nt++) {
            int c = n_base + nt * 8 + tig * 2;
            float b0 = __ldg(bias + c), b1 = __ldg(bias + c + 1);
            if (r < NP) {
                float2 v = make_float2(acc[mt][nt][0] * INV_SAB + b0,
                                       acc[mt][nt][1] * INV_SAB + b1);
                *(float2*)(out + (size_t)r * 64 + c) = v;
            }
            if (r8 < NP) {
                float2 v = make_float2(acc[mt][nt][2] * INV_SAB + b0,
                                       acc[mt][nt][3] * INV_SAB + b1);
                *(float2*)(out + (size_t)r8 * 64 + c) = v;
            }
        }
    }
}

// ===================== launch =====================
extern "C" void kernel_launch(void* const* d_in, const int* in_sizes, int n_in,
                              void* d_out, int out_size) {
    const float* feat = (const float*)d_in[0];
    const int*   recv = (const int*)d_in[1];
    const float* rp   = (const float*)d_in[2];
    const float* ws   = (const float*)d_in[3];
    const int*   snd  = (const int*)d_in[4];
    const float* ker  = (const float*)d_in[5];
    const float* bias = (const float*)d_in[6];
    float* out = (float*)d_out;

    cudaFuncSetAttribute(k_gemm, cudaFuncAttributeMaxDynamicSharedMemorySize, GEMM_SMEM);

    k_prep<<<(NPAD + 255) / 256, 256>>>(ker);
    k_fill<<<(EDG + 255) / 256, 256>>>(recv, snd, rp, ws);
    k_phase1<<<NPAD / 2, 64>>>(feat);
    k_gemm<<<NPAD / 128, 256, GEMM_SMEM>>>(bias, out);
}